// round 15
// baseline (speedup 1.0000x reference)
#include <cuda_runtime.h>
#include <cuda_fp16.h>
#include <math.h>
#include <stdint.h>

namespace {

constexpr int Bb  = 8;
constexpr int Hh  = 112;
constexpr int Ww  = 112;
constexpr int C   = 192;
constexpr int NH  = 6;
constexpr int HD  = 32;      // C / NH
constexpr int WS  = 7;
constexpr int SS  = 3;
constexpr int N   = 49;      // WS*WS
constexpr int WG  = Hh / WS; // 16
constexpr int NW  = WG * WG; // 256
constexpr int BW  = Bb * NW; // 2048
constexpr int T   = BW * N;  // 100352 tokens
constexpr int C4  = 4 * C;   // 768
constexpr int QKVC = 3 * C;  // 576
constexpr float EPS    = 1e-5f;
constexpr float LOG100 = 4.605170185988091f;

// ---------------- scratch (static device globals; no allocation) -----------
__device__ __half g_xh   [(size_t)T * C];    // input x as half (natural layout)
__device__ __half g_qkvh [(size_t)T * QKVC]; // fused q|k|v, half (window layout)
__device__ __half g_winh [(size_t)T * C];    // attn output, half (window layout)
__device__ float  g_q    [(size_t)T * C];    // proj output
__device__ float  g_k    [(size_t)T * C];    // hidden fp32 (natural layout)
__device__ __half g_kh   [(size_t)T * C];    // hidden half (natural layout)
__device__ float  g_v    [(size_t)T * C];    // mlp output
__device__ __half g_mlp1h[(size_t)T * C4];   // fc1 output, half
__device__ __half g_wqkvT[QKVC * C];         // packed qkv weight, transposed, half
__device__ __half g_pwT  [C * C];            // proj weight transposed
__device__ __half g_fc1T [C4 * C];           // fc1 weight transposed
__device__ __half g_fc2T [C * C4];           // fc2 weight transposed
__device__ float g_bqkv[QKVC];               // packed qkv bias
__device__ float g_cpb [169 * NH];           // 16*sigmoid(CPB bias) table
__device__ float g_scl [NH];                 // per-head logit scale

// ---------------- CPB bias table MLP: (169,2)->512(relu)->NH ---------------
__global__ void cpb_kernel(const float* __restrict__ w0, const float* __restrict__ b0,
                           const float* __restrict__ w1, const float* __restrict__ ls) {
    int r   = blockIdx.x;     // 0..168
    int tid = threadIdx.x;    // 256 threads
    __shared__ float part[256][NH];

    int ri = r / 13, rj = r % 13;
    float t0 = (ri - 6) * (8.0f / 6.0f);
    float t1 = (rj - 6) * (8.0f / 6.0f);
    float v0 = copysignf(log2f(fabsf(t0) + 1.0f) * (1.0f / 3.0f), t0);
    float v1 = copysignf(log2f(fabsf(t1) + 1.0f) * (1.0f / 3.0f), t1);

    float acc[NH];
    #pragma unroll
    for (int h = 0; h < NH; ++h) acc[h] = 0.0f;
    for (int j = tid; j < 512; j += 256) {
        float hv = fmaxf(v0 * w0[j] + v1 * w0[512 + j] + b0[j], 0.0f);
        #pragma unroll
        for (int h = 0; h < NH; ++h) acc[h] += hv * w1[j * NH + h];
    }
    #pragma unroll
    for (int h = 0; h < NH; ++h) part[tid][h] = acc[h];
    __syncthreads();
    if (tid < NH) {
        float s = 0.0f;
        for (int i = 0; i < 256; ++i) s += part[i][tid];
        g_cpb[r * NH + tid] = 16.0f / (1.0f + expf(-s));
        if (r == 0) g_scl[tid] = expf(fminf(ls[tid], LOG100));
    }
}

// ---------------- x -> half convert (natural layout) ------------------------
__global__ void cvtx_kernel(const float* __restrict__ x) {
    size_t i = ((size_t)blockIdx.x * blockDim.x + threadIdx.x) * 4;
    if (i >= (size_t)T * C) return;
    float4 u = *reinterpret_cast<const float4*>(x + i);
    __half2 h0 = __floats2half2_rn(u.x, u.y);
    __half2 h1 = __floats2half2_rn(u.z, u.w);
    uint2 p = make_uint2(*reinterpret_cast<uint32_t*>(&h0),
                         *reinterpret_cast<uint32_t*>(&h1));
    *reinterpret_cast<uint2*>(g_xh + i) = p;
}

// ---------------- weight packing: transpose to half [Nn][K] ----------------
__global__ void packT_kernel(const float* __restrict__ W, __half* __restrict__ WT,
                             int K, int Nn) {
    int n = blockIdx.x;           // 0..Nn-1
    for (int k = threadIdx.x; k < K; k += blockDim.x)
        WT[(size_t)n * K + k] = __float2half(W[(size_t)k * Nn + n]);
}

__global__ void packqkvT_kernel(const float* __restrict__ qw, const float* __restrict__ kw,
                                const float* __restrict__ vw, const float* __restrict__ qb,
                                const float* __restrict__ vb) {
    int j = blockIdx.x;           // 0..575
    const float* src; int jj;
    if (j < C)            { src = qw; jj = j; }
    else if (j < 2 * C)   { src = kw; jj = j - C; }
    else                  { src = vw; jj = j - 2 * C; }
    for (int k = threadIdx.x; k < C; k += blockDim.x)
        g_wqkvT[(size_t)j * C + k] = __float2half(src[(size_t)k * C + jj]);
    if (threadIdx.x == 0) {
        float b;
        if (j < C)          b = qb[j];
        else if (j < 2 * C) b = 0.0f;
        else                b = vb[j - 2 * C];
        g_bqkv[j] = b;
    }
}

// ---------------- fp16 tensor-core GEMM: C = act(A@B + bias) ---------------
// A: half [M][K] (optional shift-window row gather). BT: half [Nn][K].
// cp.async 3-stage pipeline, GBK=32, one __syncthreads per K-tile.
constexpr int GBM = 128, GBN = 64, GBK = 32, STAGES = 3;
constexpr int AST = 40;   // half stride per A row (32 + 8 pad)
constexpr int BST = 40;   // half stride per B col
constexpr int ASTAGE = GBM * AST;  // halves per A stage
constexpr int BSTAGE = GBN * BST;  // halves per B stage

__device__ __forceinline__ float gelu_tanh(float v) {
    return 0.5f * v * (1.0f + tanhf(0.7978845608028654f * (v + 0.044715f * v * v * v)));
}

__device__ __forceinline__ void mma_f16(float* d, const uint32_t* a, const uint32_t* b) {
    asm volatile(
        "mma.sync.aligned.m16n8k16.row.col.f32.f16.f16.f32 "
        "{%0,%1,%2,%3},{%4,%5,%6,%7},{%8,%9},{%0,%1,%2,%3};"
        : "+f"(d[0]), "+f"(d[1]), "+f"(d[2]), "+f"(d[3])
        : "r"(a[0]), "r"(a[1]), "r"(a[2]), "r"(a[3]), "r"(b[0]), "r"(b[1]));
}

__device__ __forceinline__ uint32_t pack_half2(float x, float y) {
    __half2 h = __floats2half2_rn(x, y);
    return *reinterpret_cast<uint32_t*>(&h);
}

__device__ __forceinline__ void cp_async16(uint32_t saddr, const void* g) {
    asm volatile("cp.async.cg.shared.global [%0], [%1], 16;" :: "r"(saddr), "l"(g));
}

__global__ __launch_bounds__(128)
void h16gemm_kernel(const __half* __restrict__ A, const __half* __restrict__ BT,
                    const float* __restrict__ bias, float* __restrict__ Cout,
                    __half* __restrict__ CoutH,
                    int M, int Nn, int K, int act, int gatherA) {
    __shared__ __half As[STAGES][ASTAGE];
    __shared__ __half Bs[STAGES][BSTAGE];

    int tid  = threadIdx.x;            // 0..127
    int lane = tid & 31;
    int warp = tid >> 5;               // 0..3
    int gid  = lane >> 2;              // 0..7
    int tg   = lane & 3;               // 0..3
    int bm = blockIdx.y * GBM;
    int bn = blockIdx.x * GBN;
    int warp_m = (warp >> 1) * 64;     // 0 or 64
    int warp_n = (warp & 1) * 32;      // 0 or 32

    // A staging: 4 x 16B chunks per thread per tile (128 rows x 32 halves)
    const __half* aSrc[4];
    uint32_t aOff[4];                  // half-offset within stage
    #pragma unroll
    for (int i = 0; i < 4; ++i) {
        int idx = tid + i * 128;        // uint4 index within tile
        int row = idx >> 2;             // 4 uint4 per row
        int k8  = (idx & 3) * 8;
        aOff[i] = row * AST + k8;
        int r = bm + row;
        size_t abase;
        if (gatherA) {
            int bw = r / N, n = r % N;
            int b  = bw / NW, w_ = bw % NW;
            int wy = w_ / WG, wx = w_ % WG;
            int hh = wy * WS + n / WS, ww = wx * WS + n % WS;
            int oh = (hh + SS) % Hh, ow = (ww + SS) % Ww;
            abase = ((size_t)(b * Hh + oh) * Ww + ow) * (size_t)K;
        } else {
            abase = (size_t)r * K;
        }
        aSrc[i] = A + abase + k8;
    }
    // B staging: 2 x 16B chunks per thread per tile (64 cols x 32 halves)
    const __half* bSrc[2];
    uint32_t bOff[2];
    #pragma unroll
    for (int i = 0; i < 2; ++i) {
        int idx = tid + i * 128;
        int col = idx >> 2;
        int k8  = (idx & 3) * 8;
        bOff[i] = col * BST + k8;
        bSrc[i] = BT + (size_t)(bn + col) * K + k8;
    }

    uint32_t asBase = (uint32_t)__cvta_generic_to_shared(&As[0][0]);
    uint32_t bsBase = (uint32_t)__cvta_generic_to_shared(&Bs[0][0]);

    float acc[4][4][4];
    #pragma unroll
    for (int mt = 0; mt < 4; ++mt)
        #pragma unroll
        for (int nt = 0; nt < 4; ++nt)
            #pragma unroll
            for (int e = 0; e < 4; ++e) acc[mt][nt][e] = 0.0f;

    int nTiles = K / GBK;

    // prologue: issue stages 0 and 1
    {
        #pragma unroll
        for (int i = 0; i < 4; ++i)
            cp_async16(asBase + aOff[i] * 2, aSrc[i]);
        #pragma unroll
        for (int i = 0; i < 2; ++i)
            cp_async16(bsBase + bOff[i] * 2, bSrc[i]);
        asm volatile("cp.async.commit_group;");
        if (nTiles > 1) {
            #pragma unroll
            for (int i = 0; i < 4; ++i)
                cp_async16(asBase + (ASTAGE + aOff[i]) * 2, aSrc[i] + GBK);
            #pragma unroll
            for (int i = 0; i < 2; ++i)
                cp_async16(bsBase + (BSTAGE + bOff[i]) * 2, bSrc[i] + GBK);
        }
        asm volatile("cp.async.commit_group;");
    }

    int stage = 0;
    for (int it = 0; it < nTiles; ++it) {
        asm volatile("cp.async.wait_group 1;");
        __syncthreads();

        // issue tile it+2 into stage (it+2)%3
        int nxt = it + 2;
        if (nxt < nTiles) {
            int ns = nxt - (nxt / STAGES) * STAGES;
            int off = nxt * GBK;
            #pragma unroll
            for (int i = 0; i < 4; ++i)
                cp_async16(asBase + (ns * ASTAGE + aOff[i]) * 2, aSrc[i] + off);
            #pragma unroll
            for (int i = 0; i < 2; ++i)
                cp_async16(bsBase + (ns * BSTAGE + bOff[i]) * 2, bSrc[i] + off);
        }
        asm volatile("cp.async.commit_group;");

        // compute: two k16 chunks from current stage
        const __half* as = As[stage];
        const __half* bs = Bs[stage];
        #pragma unroll
        for (int kk = 0; kk < GBK; kk += 16) {
            uint32_t af[4][4];
            #pragma unroll
            for (int mt = 0; mt < 4; ++mt) {
                int r0 = warp_m + mt * 16 + gid;
                af[mt][0] = *reinterpret_cast<const uint32_t*>(&as[ r0      * AST + kk + tg * 2    ]);
                af[mt][1] = *reinterpret_cast<const uint32_t*>(&as[(r0 + 8) * AST + kk + tg * 2    ]);
                af[mt][2] = *reinterpret_cast<const uint32_t*>(&as[ r0      * AST + kk + tg * 2 + 8]);
                af[mt][3] = *reinterpret_cast<const uint32_t*>(&as[(r0 + 8) * AST + kk + tg * 2 + 8]);
            }
            uint32_t bf[4][2];
            #pragma unroll
            for (int nt = 0; nt < 4; ++nt) {
                int c0 = warp_n + nt * 8 + gid;
                bf[nt][0] = *reinterpret_cast<const uint32_t*>(&bs[c0 * BST + kk + tg * 2    ]);
                bf[nt][1] = *reinterpret_cast<const uint32_t*>(&bs[c0 * BST + kk + tg * 2 + 8]);
            }
            #pragma unroll
            for (int mt = 0; mt < 4; ++mt)
                #pragma unroll
                for (int nt = 0; nt < 4; ++nt)
                    mma_f16(acc[mt][nt], af[mt], bf[nt]);
        }
        if (++stage == STAGES) stage = 0;
    }

    // epilogue: bias + optional GELU; float2 or half2 stores (col even)
    #pragma unroll
    for (int mt = 0; mt < 4; ++mt) {
        #pragma unroll
        for (int r2 = 0; r2 < 2; ++r2) {
            int row = bm + warp_m + mt * 16 + gid + r2 * 8;
            #pragma unroll
            for (int nt = 0; nt < 4; ++nt) {
                int col = bn + warp_n + nt * 8 + tg * 2;
                float v0 = acc[mt][nt][r2 * 2 + 0];
                float v1 = acc[mt][nt][r2 * 2 + 1];
                if (bias) { v0 += bias[col]; v1 += bias[col + 1]; }
                if (act == 1) { v0 = gelu_tanh(v0); v1 = gelu_tanh(v1); }
                if (CoutH)
                    *reinterpret_cast<uint32_t*>(&CoutH[(size_t)row * Nn + col]) =
                        pack_half2(v0, v1);
                else
                    *reinterpret_cast<float2*>(&Cout[(size_t)row * Nn + col]) =
                        make_float2(v0, v1);
            }
        }
    }
}

// ---------------- fused per-(window,head) attention (tensor cores) ---------
constexpr int QKS = 40;   // half stride of qh/kh rows (20 uint32)
constexpr int VTS = 72;   // half stride of vT rows (36 uint32)

__global__ __launch_bounds__(128)
void attn_kernel() {
    int blk = blockIdx.x;          // 0..BW*NH-1
    int bw  = blk / NH, h = blk % NH;
    int tid = threadIdx.x;
    int warp = tid >> 5, lane = tid & 31;
    int gid  = lane >> 2, tg = lane & 3;

    __shared__ __half qh[64 * QKS];
    __shared__ __half kh[64 * QKS];
    __shared__ __half vT[32 * VTS];
    __shared__ float cpb_s[169];
    __shared__ int   joff_s[64];
    __shared__ int   rgn_s[64];
    __shared__ float scale_s;

    uint32_t* qh32 = reinterpret_cast<uint32_t*>(qh);
    uint32_t* kh32 = reinterpret_cast<uint32_t*>(kh);
    uint32_t* vT32 = reinterpret_cast<uint32_t*>(vT);

    for (int i = tid; i < 64 * QKS / 2; i += 128) { qh32[i] = 0u; kh32[i] = 0u; }
    for (int i = tid; i < 32 * VTS / 2; i += 128) vT32[i] = 0u;

    if (tid == 0) scale_s = g_scl[h];
    for (int r = tid; r < 169; r += 128) cpb_s[r] = g_cpb[r * NH + h];
    if (tid < 64) {
        int j = tid;
        if (j < N) {
            int jy = j / WS, jx = j % WS;
            joff_s[j] = (6 - jy) * 13 + (6 - jx);
            int w_ = bw % NW, wy = w_ / WG, wx = w_ % WG;
            int gh = wy * WS + jy, gw = wx * WS + jx;
            int rh = gh < Hh - WS ? 0 : (gh < Hh - SS ? 1 : 2);
            int rw = gw < Ww - WS ? 0 : (gw < Ww - SS ? 1 : 2);
            rgn_s[j] = rh * 3 + rw;
        } else { joff_s[j] = 0; rgn_s[j] = -1; }
    }
    __syncthreads();

    // normalize q/k rows (loaded as half, accumulated fp32) and store as half
    if (tid < 2 * N) {
        int isK = tid >= N;
        int r = isK ? tid - N : tid;
        const __half* row = g_qkvh + (size_t)(bw * N + r) * QKVC + h * HD + (isK ? C : 0);
        float2 u[16];
        float ssum = 0.0f;
        #pragma unroll
        for (int d2 = 0; d2 < 16; ++d2) {
            __half2 hv = *reinterpret_cast<const __half2*>(row + d2 * 2);
            u[d2] = __half22float2(hv);
            ssum += u[d2].x * u[d2].x + u[d2].y * u[d2].y;
        }
        float inv = 1.0f / fmaxf(sqrtf(ssum), 1e-12f);
        if (!isK) inv *= scale_s;
        uint32_t* dst = (isK ? kh32 : qh32) + r * (QKS / 2);
        #pragma unroll
        for (int d2 = 0; d2 < 16; ++d2)
            dst[d2] = pack_half2(u[d2].x * inv, u[d2].y * inv);
    }
    // v transposed into vT[dim][token] (half copy)
    for (int e = tid; e < N * HD; e += 128) {
        int tok = e >> 5, d = e & 31;
        vT[d * VTS + tok] = g_qkvh[(size_t)(bw * N + tok) * QKVC + 2 * C + h * HD + d];
    }
    __syncthreads();

    int m0 = warp * 16;
    int r0 = m0 + gid, r1 = r0 + 8;

    // ---- S = Q @ K^T  (16 x 64 per warp) ----
    float sacc[8][4];
    #pragma unroll
    for (int nt = 0; nt < 8; ++nt)
        #pragma unroll
        for (int e = 0; e < 4; ++e) sacc[nt][e] = 0.0f;

    #pragma unroll
    for (int ks = 0; ks < 2; ++ks) {
        uint32_t a[4];
        a[0] = qh32[ r0       * (QKS / 2) + ks * 8 + tg    ];
        a[1] = qh32[ r1       * (QKS / 2) + ks * 8 + tg    ];
        a[2] = qh32[ r0       * (QKS / 2) + ks * 8 + tg + 4];
        a[3] = qh32[ r1       * (QKS / 2) + ks * 8 + tg + 4];
        #pragma unroll
        for (int nt = 0; nt < 8; ++nt) {
            uint32_t b[2];
            int jr = nt * 8 + gid;
            b[0] = kh32[jr * (QKS / 2) + ks * 8 + tg    ];
            b[1] = kh32[jr * (QKS / 2) + ks * 8 + tg + 4];
            mma_f16(sacc[nt], a, b);
        }
    }

    // ---- bias + mask + softmax ----
    int ib0 = (r0 < N) ? (r0 / WS) * 13 + (r0 % WS) : 0;
    int ib1 = (r1 < N) ? (r1 / WS) * 13 + (r1 % WS) : 0;
    int rg0 = (r0 < N) ? rgn_s[r0] : -2;
    int rg1 = (r1 < N) ? rgn_s[r1] : -2;

    float mx0 = -1e30f, mx1 = -1e30f;
    #pragma unroll
    for (int nt = 0; nt < 8; ++nt) {
        int j0 = nt * 8 + tg * 2, j1 = j0 + 1;
        int jo0 = joff_s[j0], jo1 = joff_s[j1];
        int rj0 = rgn_s[j0],  rj1 = rgn_s[j1];
        float v00 = (j0 < N) ? sacc[nt][0] + cpb_s[ib0 + jo0] + (rj0 == rg0 ? 0.f : -100.f) : -1e30f;
        float v01 = (j1 < N) ? sacc[nt][1] + cpb_s[ib0 + jo1] + (rj1 == rg0 ? 0.f : -100.f) : -1e30f;
        float v10 = (j0 < N) ? sacc[nt][2] + cpb_s[ib1 + jo0] + (rj0 == rg1 ? 0.f : -100.f) : -1e30f;
        float v11 = (j1 < N) ? sacc[nt][3] + cpb_s[ib1 + jo1] + (rj1 == rg1 ? 0.f : -100.f) : -1e30f;
        sacc[nt][0] = v00; sacc[nt][1] = v01; sacc[nt][2] = v10; sacc[nt][3] = v11;
        mx0 = fmaxf(mx0, fmaxf(v00, v01));
        mx1 = fmaxf(mx1, fmaxf(v10, v11));
    }
    mx0 = fmaxf(mx0, __shfl_xor_sync(0xffffffffu, mx0, 1));
    mx0 = fmaxf(mx0, __shfl_xor_sync(0xffffffffu, mx0, 2));
    mx1 = fmaxf(mx1, __shfl_xor_sync(0xffffffffu, mx1, 1));
    mx1 = fmaxf(mx1, __shfl_xor_sync(0xffffffffu, mx1, 2));

    float sm0 = 0.0f, sm1 = 0.0f;
    #pragma unroll
    for (int nt = 0; nt < 8; ++nt) {
        sacc[nt][0] = __expf(sacc[nt][0] - mx0);
        sacc[nt][1] = __expf(sacc[nt][1] - mx0);
        sacc[nt][2] = __expf(sacc[nt][2] - mx1);
        sacc[nt][3] = __expf(sacc[nt][3] - mx1);
        sm0 += sacc[nt][0] + sacc[nt][1];
        sm1 += sacc[nt][2] + sacc[nt][3];
    }
    sm0 += __shfl_xor_sync(0xffffffffu, sm0, 1);
    sm0 += __shfl_xor_sync(0xffffffffu, sm0, 2);
    sm1 += __shfl_xor_sync(0xffffffffu, sm1, 1);
    sm1 += __shfl_xor_sync(0xffffffffu, sm1, 2);
    float inv0 = 1.0f / sm0, inv1 = 1.0f / sm1;

    uint32_t ph0[8], ph1[8];
    #pragma unroll
    for (int nt = 0; nt < 8; ++nt) {
        ph0[nt] = pack_half2(sacc[nt][0] * inv0, sacc[nt][1] * inv0);
        ph1[nt] = pack_half2(sacc[nt][2] * inv1, sacc[nt][3] * inv1);
    }

    // ---- O = P @ V  (16 x 32 per warp) ----
    float oacc[4][4];
    #pragma unroll
    for (int nt = 0; nt < 4; ++nt)
        #pragma unroll
        for (int e = 0; e < 4; ++e) oacc[nt][e] = 0.0f;

    #pragma unroll
    for (int ks = 0; ks < 4; ++ks) {
        uint32_t a[4];
        a[0] = ph0[2 * ks];
        a[1] = ph1[2 * ks];
        a[2] = ph0[2 * ks + 1];
        a[3] = ph1[2 * ks + 1];
        #pragma unroll
        for (int nt = 0; nt < 4; ++nt) {
            uint32_t b[2];
            int dr = nt * 8 + gid;
            b[0] = vT32[dr * (VTS / 2) + ks * 8 + tg    ];
            b[1] = vT32[dr * (VTS / 2) + ks * 8 + tg + 4];
            mma_f16(oacc[nt], a, b);
        }
    }

    // store as half (proj GEMM consumes half A)
    __half* dst = g_winh + (size_t)bw * N * C + h * HD;
    #pragma unroll
    for (int nt = 0; nt < 4; ++nt) {
        int d0 = nt * 8 + tg * 2;
        if (r0 < N)
            *reinterpret_cast<uint32_t*>(&dst[(size_t)r0 * C + d0]) =
                pack_half2(oacc[nt][0], oacc[nt][1]);
        if (r1 < N)
            *reinterpret_cast<uint32_t*>(&dst[(size_t)r1 * C + d0]) =
                pack_half2(oacc[nt][2], oacc[nt][3]);
    }
}

// ---------------- warp-per-token LN kernels ---------------------------------
__device__ __forceinline__ float warp_sum(float v) {
    #pragma unroll
    for (int o = 16; o > 0; o >>= 1) v += __shfl_xor_sync(0xffffffffu, v, o);
    return v;
}

// hidden[dst] = x[dst] + LN1(proj[t]); fp32 + half copies. 8 tokens/block.
__global__ __launch_bounds__(256)
void postattn_kernel(const float* __restrict__ x,
                     const float* __restrict__ g1, const float* __restrict__ b1) {
    int warp = threadIdx.x >> 5, lane = threadIdx.x & 31;
    int t = blockIdx.x * 8 + warp;
    int bw = t / N, n = t % N;
    int b  = bw / NW, w_ = bw % NW;
    int wy = w_ / WG, wx = w_ % WG;
    int hh = wy * WS + n / WS, ww = wx * WS + n % WS;
    int oh = (hh + SS) % Hh, ow = (ww + SS) % Ww;
    size_t dst = ((size_t)(b * Hh + oh) * Ww + ow) * C;

    const float* src = g_q + (size_t)t * C;
    float v[6];
    float s = 0.0f;
    #pragma unroll
    for (int i = 0; i < 6; ++i) { v[i] = src[lane + i * 32]; s += v[i]; }
    float mean = warp_sum(s) * (1.0f / C);
    float vr = 0.0f;
    #pragma unroll
    for (int i = 0; i < 6; ++i) { float d = v[i] - mean; vr += d * d; }
    float rsig = rsqrtf(warp_sum(vr) * (1.0f / C) + EPS);
    #pragma unroll
    for (int i = 0; i < 6; ++i) {
        int c = lane + i * 32;
        float ln = (v[i] - mean) * rsig * g1[c] + b1[c];
        float hv = x[dst + c] + ln;
        g_k [dst + c] = hv;
        g_kh[dst + c] = __float2half(hv);
    }
}

// out[t] = hidden[t] + LN2(mlp[t]). 8 tokens/block.
__global__ __launch_bounds__(256)
void final_kernel(const float* __restrict__ g2, const float* __restrict__ b2,
                  float* __restrict__ out) {
    int warp = threadIdx.x >> 5, lane = threadIdx.x & 31;
    int t = blockIdx.x * 8 + warp;
    const float* src = g_v + (size_t)t * C;
    float v[6];
    float s = 0.0f;
    #pragma unroll
    for (int i = 0; i < 6; ++i) { v[i] = src[lane + i * 32]; s += v[i]; }
    float mean = warp_sum(s) * (1.0f / C);
    float vr = 0.0f;
    #pragma unroll
    for (int i = 0; i < 6; ++i) { float d = v[i] - mean; vr += d * d; }
    float rsig = rsqrtf(warp_sum(vr) * (1.0f / C) + EPS);
    #pragma unroll
    for (int i = 0; i < 6; ++i) {
        int c = lane + i * 32;
        float ln = (v[i] - mean) * rsig * g2[c] + b2[c];
        out[(size_t)t * C + c] = g_k[(size_t)t * C + c] + ln;
    }
}

} // namespace

// ============================================================================
extern "C" void kernel_launch(void* const* d_in, const int* in_sizes, int n_in,
                              void* d_out, int out_size) {
    const float* x      = (const float*)d_in[0];
    const float* ln1_g  = (const float*)d_in[1];
    const float* ln1_b  = (const float*)d_in[2];
    const float* ln2_g  = (const float*)d_in[3];
    const float* ln2_b  = (const float*)d_in[4];
    const float* q_w    = (const float*)d_in[5];
    const float* q_b    = (const float*)d_in[6];
    const float* k_w    = (const float*)d_in[7];
    const float* v_w    = (const float*)d_in[8];
    const float* v_b    = (const float*)d_in[9];
    const float* p_w    = (const float*)d_in[10];
    const float* p_b    = (const float*)d_in[11];
    const float* lscale = (const float*)d_in[12];
    const float* cpb_w0 = (const float*)d_in[13];
    const float* cpb_b0 = (const float*)d_in[14];
    const float* cpb_w1 = (const float*)d_in[15];
    const float* fc1_w  = (const float*)d_in[16];
    const float* fc1_b  = (const float*)d_in[17];
    const float* fc2_w  = (const float*)d_in[18];
    const float* fc2_b  = (const float*)d_in[19];
    float* out = (float*)d_out;

    float *p_q, *p_v, *p_bqkv;
    __half *p_xh, *p_qkvh, *p_winh, *p_kh, *p_m1h, *p_wqkvT, *p_pwT, *p_fc1T, *p_fc2T;
    cudaGetSymbolAddress((void**)&p_xh,    g_xh);
    cudaGetSymbolAddress((void**)&p_qkvh,  g_qkvh);
    cudaGetSymbolAddress((void**)&p_winh,  g_winh);
    cudaGetSymbolAddress((void**)&p_q,     g_q);
    cudaGetSymbolAddress((void**)&p_kh,    g_kh);
    cudaGetSymbolAddress((void**)&p_v,     g_v);
    cudaGetSymbolAddress((void**)&p_m1h,   g_mlp1h);
    cudaGetSymbolAddress((void**)&p_bqkv,  g_bqkv);
    cudaGetSymbolAddress((void**)&p_wqkvT, g_wqkvT);
    cudaGetSymbolAddress((void**)&p_pwT,   g_pwT);
    cudaGetSymbolAddress((void**)&p_fc1T,  g_fc1T);
    cudaGetSymbolAddress((void**)&p_fc2T,  g_fc2T);

    // 1) CPB table + scales; x->half; pack/transpose weights to half
    cpb_kernel<<<169, 256>>>(cpb_w0, cpb_b0, cpb_w1, lscale);
    cvtx_kernel<<<(T * C / 4 + 255) / 256, 256>>>(x);
    packqkvT_kernel<<<QKVC, 192>>>(q_w, k_w, v_w, q_b, v_b);
    packT_kernel<<<C,  192>>>(p_w,   p_pwT,  C,  C);
    packT_kernel<<<C4, 192>>>(fc1_w, p_fc1T, C,  C4);
    packT_kernel<<<C,  192>>>(fc2_w, p_fc2T, C4, C);

    // 2) fused shift+window-gather + QKV GEMM -> half output
    dim3 gQKV(QKVC / GBN, T / GBM);
    h16gemm_kernel<<<gQKV, 128>>>(p_xh, p_wqkvT, p_bqkv, nullptr, p_qkvh,
                                  T, QKVC, C, 0, 1);

    // 3) fused attention -> g_winh (half)
    attn_kernel<<<BW * NH, 128>>>();

    // 4) output projection (A = attn out, half) -> g_q fp32
    dim3 gC(C / GBN, T / GBM);
    h16gemm_kernel<<<gC, 128>>>(p_winh, p_pwT, p_b, p_q, nullptr,
                                T, C, C, 0, 0);

    // 5) window reverse + un-shift + LN1 + residual -> hidden fp32 + half
    postattn_kernel<<<T / 8, 256>>>(x, ln1_g, ln1_b);

    // 6) fc1 + GELU (A = hidden half) -> g_mlp1h half
    dim3 gF1(C4 / GBN, T / GBM);
    h16gemm_kernel<<<gF1, 128>>>(p_kh, p_fc1T, fc1_b, nullptr, p_m1h,
                                 T, C4, C, 1, 0);

    // 7) fc2 (A = mlp1 half) -> g_v fp32
    h16gemm_kernel<<<gC, 128>>>(p_m1h, p_fc2T, fc2_b, p_v, nullptr,
                                T, C, C4, 0, 0);

    // 8) hidden + LN2(mlp) -> out
    final_kernel<<<T / 8, 256>>>(ln2_g, ln2_b, out);
}

// round 16
// speedup vs baseline: 1.0401x; 1.0401x over previous
#include <cuda_runtime.h>
#include <cuda_fp16.h>
#include <math.h>
#include <stdint.h>

namespace {

constexpr int Bb  = 8;
constexpr int Hh  = 112;
constexpr int Ww  = 112;
constexpr int C   = 192;
constexpr int NH  = 6;
constexpr int HD  = 32;      // C / NH
constexpr int WS  = 7;
constexpr int SS  = 3;
constexpr int N   = 49;      // WS*WS
constexpr int WG  = Hh / WS; // 16
constexpr int NW  = WG * WG; // 256
constexpr int BW  = Bb * NW; // 2048
constexpr int T   = BW * N;  // 100352 tokens
constexpr int C4  = 4 * C;   // 768
constexpr int QKVC = 3 * C;  // 576
constexpr float EPS    = 1e-5f;
constexpr float LOG100 = 4.605170185988091f;

// ---------------- scratch (static device globals; no allocation) -----------
__device__ __half g_xh   [(size_t)T * C];    // input x as half (natural layout)
__device__ float  g_qkv  [(size_t)T * QKVC]; // fused q|k|v (window-token layout)
__device__ __half g_winh [(size_t)T * C];    // attn output, half (window layout)
__device__ float  g_q    [(size_t)T * C];    // proj output
__device__ float  g_k    [(size_t)T * C];    // hidden fp32 (natural layout)
__device__ __half g_kh   [(size_t)T * C];    // hidden half (natural layout)
__device__ float  g_v    [(size_t)T * C];    // mlp output
__device__ __half g_mlp1h[(size_t)T * C4];   // fc1 output, half
__device__ __half g_wqkvT[QKVC * C];         // packed qkv weight, transposed, half
__device__ __half g_pwT  [C * C];            // proj weight transposed
__device__ __half g_fc1T [C4 * C];           // fc1 weight transposed
__device__ __half g_fc2T [C * C4];           // fc2 weight transposed
__device__ float g_bqkv[QKVC];               // packed qkv bias
__device__ float g_cpb [169 * NH];           // 16*sigmoid(CPB bias) table
__device__ float g_scl [NH];                 // per-head logit scale

__device__ __forceinline__ uint32_t pack_half2(float x, float y) {
    __half2 h = __floats2half2_rn(x, y);
    return *reinterpret_cast<uint32_t*>(&h);
}

// ================= merged prep kernel (one launch, block-range dispatch) ====
// ranges: [0, NB_CVT) cvtx | [+169) cpb | [+576) packqkvT | [+192) pw
//         [+768) fc1 | [+192) fc2
constexpr int NB_CVT = (int)((size_t)T * C / 4 / 256);  // 18816
constexpr int B_CPB0 = NB_CVT;
constexpr int B_QKV0 = B_CPB0 + 169;
constexpr int B_PW0  = B_QKV0 + QKVC;
constexpr int B_FC10 = B_PW0 + C;
constexpr int B_FC20 = B_FC10 + C4;
constexpr int NB_PREP = B_FC20 + C;

__global__ __launch_bounds__(256)
void prep_kernel(const float* __restrict__ x,
                 const float* __restrict__ cpb_w0, const float* __restrict__ cpb_b0,
                 const float* __restrict__ cpb_w1, const float* __restrict__ ls,
                 const float* __restrict__ qw, const float* __restrict__ kw,
                 const float* __restrict__ vw, const float* __restrict__ qb,
                 const float* __restrict__ vb,
                 const float* __restrict__ pw,
                 const float* __restrict__ fc1w, const float* __restrict__ fc2w) {
    int blk = blockIdx.x;
    int tid = threadIdx.x;

    if (blk < NB_CVT) {
        // ---- x -> half ----
        size_t i = ((size_t)blk * 256 + tid) * 4;
        float4 u = *reinterpret_cast<const float4*>(x + i);
        uint2 p = make_uint2(pack_half2(u.x, u.y), pack_half2(u.z, u.w));
        *reinterpret_cast<uint2*>(g_xh + i) = p;
        return;
    }
    if (blk < B_QKV0) {
        // ---- CPB bias table MLP row ----
        int r = blk - B_CPB0;          // 0..168
        __shared__ float part[256][NH];
        int ri = r / 13, rj = r % 13;
        float t0 = (ri - 6) * (8.0f / 6.0f);
        float t1 = (rj - 6) * (8.0f / 6.0f);
        float v0 = copysignf(log2f(fabsf(t0) + 1.0f) * (1.0f / 3.0f), t0);
        float v1 = copysignf(log2f(fabsf(t1) + 1.0f) * (1.0f / 3.0f), t1);
        float acc[NH];
        #pragma unroll
        for (int h = 0; h < NH; ++h) acc[h] = 0.0f;
        for (int j = tid; j < 512; j += 256) {
            float hv = fmaxf(v0 * cpb_w0[j] + v1 * cpb_w0[512 + j] + cpb_b0[j], 0.0f);
            #pragma unroll
            for (int h = 0; h < NH; ++h) acc[h] += hv * cpb_w1[j * NH + h];
        }
        #pragma unroll
        for (int h = 0; h < NH; ++h) part[tid][h] = acc[h];
        __syncthreads();
        if (tid < NH) {
            float s = 0.0f;
            for (int i = 0; i < 256; ++i) s += part[i][tid];
            g_cpb[r * NH + tid] = 16.0f / (1.0f + expf(-s));
            if (r == 0) g_scl[tid] = expf(fminf(ls[tid], LOG100));
        }
        return;
    }
    if (blk < B_PW0) {
        // ---- packed qkv weight col -> row of g_wqkvT ----
        int j = blk - B_QKV0;          // 0..575
        const float* src; int jj;
        if (j < C)            { src = qw; jj = j; }
        else if (j < 2 * C)   { src = kw; jj = j - C; }
        else                  { src = vw; jj = j - 2 * C; }
        for (int k = tid; k < C; k += 256)
            g_wqkvT[(size_t)j * C + k] = __float2half(src[(size_t)k * C + jj]);
        if (tid == 0) {
            float b;
            if (j < C)          b = qb[j];
            else if (j < 2 * C) b = 0.0f;
            else                b = vb[j - 2 * C];
            g_bqkv[j] = b;
        }
        return;
    }
    if (blk < B_FC10) {
        int n = blk - B_PW0;           // proj: K=C, Nn=C
        for (int k = tid; k < C; k += 256)
            g_pwT[(size_t)n * C + k] = __float2half(pw[(size_t)k * C + n]);
        return;
    }
    if (blk < B_FC20) {
        int n = blk - B_FC10;          // fc1: K=C, Nn=C4
        for (int k = tid; k < C; k += 256)
            g_fc1T[(size_t)n * C + k] = __float2half(fc1w[(size_t)k * C4 + n]);
        return;
    }
    {
        int n = blk - B_FC20;          // fc2: K=C4, Nn=C
        for (int k = tid; k < C4; k += 256)
            g_fc2T[(size_t)n * C4 + k] = __float2half(fc2w[(size_t)k * C + n]);
    }
}

// ---------------- fp16 tensor-core GEMM: C = act(A@B + bias) ---------------
// A: half [M][K] (optional shift-window row gather). BT: half [Nn][K].
// cp.async 3-stage pipeline, GBK=32, one __syncthreads per K-tile.
constexpr int GBM = 128, GBN = 64, GBK = 32, STAGES = 3;
constexpr int AST = 40;   // half stride per A row (32 + 8 pad)
constexpr int BST = 40;   // half stride per B col
constexpr int ASTAGE = GBM * AST;  // halves per A stage
constexpr int BSTAGE = GBN * BST;  // halves per B stage

__device__ __forceinline__ float gelu_tanh(float v) {
    return 0.5f * v * (1.0f + tanhf(0.7978845608028654f * (v + 0.044715f * v * v * v)));
}

__device__ __forceinline__ void mma_f16(float* d, const uint32_t* a, const uint32_t* b) {
    asm volatile(
        "mma.sync.aligned.m16n8k16.row.col.f32.f16.f16.f32 "
        "{%0,%1,%2,%3},{%4,%5,%6,%7},{%8,%9},{%0,%1,%2,%3};"
        : "+f"(d[0]), "+f"(d[1]), "+f"(d[2]), "+f"(d[3])
        : "r"(a[0]), "r"(a[1]), "r"(a[2]), "r"(a[3]), "r"(b[0]), "r"(b[1]));
}

__device__ __forceinline__ void cp_async16(uint32_t saddr, const void* g) {
    asm volatile("cp.async.cg.shared.global [%0], [%1], 16;" :: "r"(saddr), "l"(g));
}

__global__ __launch_bounds__(128)
void h16gemm_kernel(const __half* __restrict__ A, const __half* __restrict__ BT,
                    const float* __restrict__ bias, float* __restrict__ Cout,
                    __half* __restrict__ CoutH,
                    int M, int Nn, int K, int act, int gatherA) {
    __shared__ __half As[STAGES][ASTAGE];
    __shared__ __half Bs[STAGES][BSTAGE];

    int tid  = threadIdx.x;            // 0..127
    int lane = tid & 31;
    int warp = tid >> 5;               // 0..3
    int gid  = lane >> 2;              // 0..7
    int tg   = lane & 3;               // 0..3
    int bm = blockIdx.y * GBM;
    int bn = blockIdx.x * GBN;
    int warp_m = (warp >> 1) * 64;     // 0 or 64
    int warp_n = (warp & 1) * 32;      // 0 or 32

    // A staging: 4 x 16B chunks per thread per tile (128 rows x 32 halves)
    const __half* aSrc[4];
    uint32_t aOff[4];                  // half-offset within stage
    #pragma unroll
    for (int i = 0; i < 4; ++i) {
        int idx = tid + i * 128;        // uint4 index within tile
        int row = idx >> 2;             // 4 uint4 per row
        int k8  = (idx & 3) * 8;
        aOff[i] = row * AST + k8;
        int r = bm + row;
        size_t abase;
        if (gatherA) {
            int bw = r / N, n = r % N;
            int b  = bw / NW, w_ = bw % NW;
            int wy = w_ / WG, wx = w_ % WG;
            int hh = wy * WS + n / WS, ww = wx * WS + n % WS;
            int oh = (hh + SS) % Hh, ow = (ww + SS) % Ww;
            abase = ((size_t)(b * Hh + oh) * Ww + ow) * (size_t)K;
        } else {
            abase = (size_t)r * K;
        }
        aSrc[i] = A + abase + k8;
    }
    // B staging: 2 x 16B chunks per thread per tile (64 cols x 32 halves)
    const __half* bSrc[2];
    uint32_t bOff[2];
    #pragma unroll
    for (int i = 0; i < 2; ++i) {
        int idx = tid + i * 128;
        int col = idx >> 2;
        int k8  = (idx & 3) * 8;
        bOff[i] = col * BST + k8;
        bSrc[i] = BT + (size_t)(bn + col) * K + k8;
    }

    uint32_t asBase = (uint32_t)__cvta_generic_to_shared(&As[0][0]);
    uint32_t bsBase = (uint32_t)__cvta_generic_to_shared(&Bs[0][0]);

    float acc[4][4][4];
    #pragma unroll
    for (int mt = 0; mt < 4; ++mt)
        #pragma unroll
        for (int nt = 0; nt < 4; ++nt)
            #pragma unroll
            for (int e = 0; e < 4; ++e) acc[mt][nt][e] = 0.0f;

    int nTiles = K / GBK;

    // prologue: issue stages 0 and 1
    {
        #pragma unroll
        for (int i = 0; i < 4; ++i)
            cp_async16(asBase + aOff[i] * 2, aSrc[i]);
        #pragma unroll
        for (int i = 0; i < 2; ++i)
            cp_async16(bsBase + bOff[i] * 2, bSrc[i]);
        asm volatile("cp.async.commit_group;");
        if (nTiles > 1) {
            #pragma unroll
            for (int i = 0; i < 4; ++i)
                cp_async16(asBase + (ASTAGE + aOff[i]) * 2, aSrc[i] + GBK);
            #pragma unroll
            for (int i = 0; i < 2; ++i)
                cp_async16(bsBase + (BSTAGE + bOff[i]) * 2, bSrc[i] + GBK);
        }
        asm volatile("cp.async.commit_group;");
    }

    int stage = 0;
    for (int it = 0; it < nTiles; ++it) {
        asm volatile("cp.async.wait_group 1;");
        __syncthreads();

        // issue tile it+2 into stage (it+2)%3
        int nxt = it + 2;
        if (nxt < nTiles) {
            int ns = nxt - (nxt / STAGES) * STAGES;
            int off = nxt * GBK;
            #pragma unroll
            for (int i = 0; i < 4; ++i)
                cp_async16(asBase + (ns * ASTAGE + aOff[i]) * 2, aSrc[i] + off);
            #pragma unroll
            for (int i = 0; i < 2; ++i)
                cp_async16(bsBase + (ns * BSTAGE + bOff[i]) * 2, bSrc[i] + off);
        }
        asm volatile("cp.async.commit_group;");

        // compute: two k16 chunks from current stage
        const __half* as = As[stage];
        const __half* bs = Bs[stage];
        #pragma unroll
        for (int kk = 0; kk < GBK; kk += 16) {
            uint32_t af[4][4];
            #pragma unroll
            for (int mt = 0; mt < 4; ++mt) {
                int r0 = warp_m + mt * 16 + gid;
                af[mt][0] = *reinterpret_cast<const uint32_t*>(&as[ r0      * AST + kk + tg * 2    ]);
                af[mt][1] = *reinterpret_cast<const uint32_t*>(&as[(r0 + 8) * AST + kk + tg * 2    ]);
                af[mt][2] = *reinterpret_cast<const uint32_t*>(&as[ r0      * AST + kk + tg * 2 + 8]);
                af[mt][3] = *reinterpret_cast<const uint32_t*>(&as[(r0 + 8) * AST + kk + tg * 2 + 8]);
            }
            uint32_t bf[4][2];
            #pragma unroll
            for (int nt = 0; nt < 4; ++nt) {
                int c0 = warp_n + nt * 8 + gid;
                bf[nt][0] = *reinterpret_cast<const uint32_t*>(&bs[c0 * BST + kk + tg * 2    ]);
                bf[nt][1] = *reinterpret_cast<const uint32_t*>(&bs[c0 * BST + kk + tg * 2 + 8]);
            }
            #pragma unroll
            for (int mt = 0; mt < 4; ++mt)
                #pragma unroll
                for (int nt = 0; nt < 4; ++nt)
                    mma_f16(acc[mt][nt], af[mt], bf[nt]);
        }
        if (++stage == STAGES) stage = 0;
    }

    // epilogue: bias + optional GELU; float2 or half2 stores (col even)
    #pragma unroll
    for (int mt = 0; mt < 4; ++mt) {
        #pragma unroll
        for (int r2 = 0; r2 < 2; ++r2) {
            int row = bm + warp_m + mt * 16 + gid + r2 * 8;
            #pragma unroll
            for (int nt = 0; nt < 4; ++nt) {
                int col = bn + warp_n + nt * 8 + tg * 2;
                float v0 = acc[mt][nt][r2 * 2 + 0];
                float v1 = acc[mt][nt][r2 * 2 + 1];
                if (bias) { v0 += bias[col]; v1 += bias[col + 1]; }
                if (act == 1) { v0 = gelu_tanh(v0); v1 = gelu_tanh(v1); }
                if (CoutH)
                    *reinterpret_cast<uint32_t*>(&CoutH[(size_t)row * Nn + col]) =
                        pack_half2(v0, v1);
                else
                    *reinterpret_cast<float2*>(&Cout[(size_t)row * Nn + col]) =
                        make_float2(v0, v1);
            }
        }
    }
}

// ---------------- fused per-(window,head) attention (tensor cores) ---------
constexpr int QKS = 40;   // half stride of qh/kh rows (20 uint32)
constexpr int VTS = 72;   // half stride of vT rows (36 uint32)

__global__ __launch_bounds__(128)
void attn_kernel() {
    int blk = blockIdx.x;          // 0..BW*NH-1
    int bw  = blk / NH, h = blk % NH;
    int tid = threadIdx.x;
    int warp = tid >> 5, lane = tid & 31;
    int gid  = lane >> 2, tg = lane & 3;

    __shared__ __half qh[64 * QKS];
    __shared__ __half kh[64 * QKS];
    __shared__ __half vT[32 * VTS];
    __shared__ float cpb_s[169];
    __shared__ int   joff_s[64];
    __shared__ int   rgn_s[64];
    __shared__ float scale_s;

    uint32_t* qh32 = reinterpret_cast<uint32_t*>(qh);
    uint32_t* kh32 = reinterpret_cast<uint32_t*>(kh);
    uint32_t* vT32 = reinterpret_cast<uint32_t*>(vT);

    for (int i = tid; i < 64 * QKS / 2; i += 128) { qh32[i] = 0u; kh32[i] = 0u; }
    for (int i = tid; i < 32 * VTS / 2; i += 128) vT32[i] = 0u;

    if (tid == 0) scale_s = g_scl[h];
    for (int r = tid; r < 169; r += 128) cpb_s[r] = g_cpb[r * NH + h];
    if (tid < 64) {
        int j = tid;
        if (j < N) {
            int jy = j / WS, jx = j % WS;
            joff_s[j] = (6 - jy) * 13 + (6 - jx);
            int w_ = bw % NW, wy = w_ / WG, wx = w_ % WG;
            int gh = wy * WS + jy, gw = wx * WS + jx;
            int rh = gh < Hh - WS ? 0 : (gh < Hh - SS ? 1 : 2);
            int rw = gw < Ww - WS ? 0 : (gw < Ww - SS ? 1 : 2);
            rgn_s[j] = rh * 3 + rw;
        } else { joff_s[j] = 0; rgn_s[j] = -1; }
    }
    __syncthreads();

    if (tid < 2 * N) {
        int isK = tid >= N;
        int r = isK ? tid - N : tid;
        const float* row = g_qkv + (size_t)(bw * N + r) * QKVC + h * HD + (isK ? C : 0);
        float4 u[8];
        float ssum = 0.0f;
        #pragma unroll
        for (int d4 = 0; d4 < 8; ++d4) {
            u[d4] = *reinterpret_cast<const float4*>(row + d4 * 4);
            ssum += u[d4].x * u[d4].x + u[d4].y * u[d4].y
                  + u[d4].z * u[d4].z + u[d4].w * u[d4].w;
        }
        float inv = 1.0f / fmaxf(sqrtf(ssum), 1e-12f);
        if (!isK) inv *= scale_s;
        uint32_t* dst = (isK ? kh32 : qh32) + r * (QKS / 2);
        #pragma unroll
        for (int d4 = 0; d4 < 8; ++d4) {
            dst[d4 * 2 + 0] = pack_half2(u[d4].x * inv, u[d4].y * inv);
            dst[d4 * 2 + 1] = pack_half2(u[d4].z * inv, u[d4].w * inv);
        }
    }
    for (int e = tid; e < N * HD; e += 128) {
        int tok = e >> 5, d = e & 31;
        float v = g_qkv[(size_t)(bw * N + tok) * QKVC + 2 * C + h * HD + d];
        vT[d * VTS + tok] = __float2half(v);
    }
    __syncthreads();

    int m0 = warp * 16;
    int r0 = m0 + gid, r1 = r0 + 8;

    // ---- S = Q @ K^T  (16 x 64 per warp) ----
    float sacc[8][4];
    #pragma unroll
    for (int nt = 0; nt < 8; ++nt)
        #pragma unroll
        for (int e = 0; e < 4; ++e) sacc[nt][e] = 0.0f;

    #pragma unroll
    for (int ks = 0; ks < 2; ++ks) {
        uint32_t a[4];
        a[0] = qh32[ r0       * (QKS / 2) + ks * 8 + tg    ];
        a[1] = qh32[ r1       * (QKS / 2) + ks * 8 + tg    ];
        a[2] = qh32[ r0       * (QKS / 2) + ks * 8 + tg + 4];
        a[3] = qh32[ r1       * (QKS / 2) + ks * 8 + tg + 4];
        #pragma unroll
        for (int nt = 0; nt < 8; ++nt) {
            uint32_t b[2];
            int jr = nt * 8 + gid;
            b[0] = kh32[jr * (QKS / 2) + ks * 8 + tg    ];
            b[1] = kh32[jr * (QKS / 2) + ks * 8 + tg + 4];
            mma_f16(sacc[nt], a, b);
        }
    }

    // ---- bias + mask + softmax ----
    int ib0 = (r0 < N) ? (r0 / WS) * 13 + (r0 % WS) : 0;
    int ib1 = (r1 < N) ? (r1 / WS) * 13 + (r1 % WS) : 0;
    int rg0 = (r0 < N) ? rgn_s[r0] : -2;
    int rg1 = (r1 < N) ? rgn_s[r1] : -2;

    float mx0 = -1e30f, mx1 = -1e30f;
    #pragma unroll
    for (int nt = 0; nt < 8; ++nt) {
        int j0 = nt * 8 + tg * 2, j1 = j0 + 1;
        int jo0 = joff_s[j0], jo1 = joff_s[j1];
        int rj0 = rgn_s[j0],  rj1 = rgn_s[j1];
        float v00 = (j0 < N) ? sacc[nt][0] + cpb_s[ib0 + jo0] + (rj0 == rg0 ? 0.f : -100.f) : -1e30f;
        float v01 = (j1 < N) ? sacc[nt][1] + cpb_s[ib0 + jo1] + (rj1 == rg0 ? 0.f : -100.f) : -1e30f;
        float v10 = (j0 < N) ? sacc[nt][2] + cpb_s[ib1 + jo0] + (rj0 == rg1 ? 0.f : -100.f) : -1e30f;
        float v11 = (j1 < N) ? sacc[nt][3] + cpb_s[ib1 + jo1] + (rj1 == rg1 ? 0.f : -100.f) : -1e30f;
        sacc[nt][0] = v00; sacc[nt][1] = v01; sacc[nt][2] = v10; sacc[nt][3] = v11;
        mx0 = fmaxf(mx0, fmaxf(v00, v01));
        mx1 = fmaxf(mx1, fmaxf(v10, v11));
    }
    mx0 = fmaxf(mx0, __shfl_xor_sync(0xffffffffu, mx0, 1));
    mx0 = fmaxf(mx0, __shfl_xor_sync(0xffffffffu, mx0, 2));
    mx1 = fmaxf(mx1, __shfl_xor_sync(0xffffffffu, mx1, 1));
    mx1 = fmaxf(mx1, __shfl_xor_sync(0xffffffffu, mx1, 2));

    float sm0 = 0.0f, sm1 = 0.0f;
    #pragma unroll
    for (int nt = 0; nt < 8; ++nt) {
        sacc[nt][0] = __expf(sacc[nt][0] - mx0);
        sacc[nt][1] = __expf(sacc[nt][1] - mx0);
        sacc[nt][2] = __expf(sacc[nt][2] - mx1);
        sacc[nt][3] = __expf(sacc[nt][3] - mx1);
        sm0 += sacc[nt][0] + sacc[nt][1];
        sm1 += sacc[nt][2] + sacc[nt][3];
    }
    sm0 += __shfl_xor_sync(0xffffffffu, sm0, 1);
    sm0 += __shfl_xor_sync(0xffffffffu, sm0, 2);
    sm1 += __shfl_xor_sync(0xffffffffu, sm1, 1);
    sm1 += __shfl_xor_sync(0xffffffffu, sm1, 2);
    float inv0 = 1.0f / sm0, inv1 = 1.0f / sm1;

    uint32_t ph0[8], ph1[8];
    #pragma unroll
    for (int nt = 0; nt < 8; ++nt) {
        ph0[nt] = pack_half2(sacc[nt][0] * inv0, sacc[nt][1] * inv0);
        ph1[nt] = pack_half2(sacc[nt][2] * inv1, sacc[nt][3] * inv1);
    }

    // ---- O = P @ V  (16 x 32 per warp) ----
    float oacc[4][4];
    #pragma unroll
    for (int nt = 0; nt < 4; ++nt)
        #pragma unroll
        for (int e = 0; e < 4; ++e) oacc[nt][e] = 0.0f;

    #pragma unroll
    for (int ks = 0; ks < 4; ++ks) {
        uint32_t a[4];
        a[0] = ph0[2 * ks];
        a[1] = ph1[2 * ks];
        a[2] = ph0[2 * ks + 1];
        a[3] = ph1[2 * ks + 1];
        #pragma unroll
        for (int nt = 0; nt < 4; ++nt) {
            uint32_t b[2];
            int dr = nt * 8 + gid;
            b[0] = vT32[dr * (VTS / 2) + ks * 8 + tg    ];
            b[1] = vT32[dr * (VTS / 2) + ks * 8 + tg + 4];
            mma_f16(oacc[nt], a, b);
        }
    }

    // store as half (proj GEMM consumes half A)
    __half* dst = g_winh + (size_t)bw * N * C + h * HD;
    #pragma unroll
    for (int nt = 0; nt < 4; ++nt) {
        int d0 = nt * 8 + tg * 2;
        if (r0 < N)
            *reinterpret_cast<uint32_t*>(&dst[(size_t)r0 * C + d0]) =
                pack_half2(oacc[nt][0], oacc[nt][1]);
        if (r1 < N)
            *reinterpret_cast<uint32_t*>(&dst[(size_t)r1 * C + d0]) =
                pack_half2(oacc[nt][2], oacc[nt][3]);
    }
}

// ---------------- warp-per-token LN kernels ---------------------------------
__device__ __forceinline__ float warp_sum(float v) {
    #pragma unroll
    for (int o = 16; o > 0; o >>= 1) v += __shfl_xor_sync(0xffffffffu, v, o);
    return v;
}

// hidden[dst] = x[dst] + LN1(proj[t]); fp32 + half copies. 8 tokens/block.
__global__ __launch_bounds__(256)
void postattn_kernel(const float* __restrict__ x,
                     const float* __restrict__ g1, const float* __restrict__ b1) {
    int warp = threadIdx.x >> 5, lane = threadIdx.x & 31;
    int t = blockIdx.x * 8 + warp;
    int bw = t / N, n = t % N;
    int b  = bw / NW, w_ = bw % NW;
    int wy = w_ / WG, wx = w_ % WG;
    int hh = wy * WS + n / WS, ww = wx * WS + n % WS;
    int oh = (hh + SS) % Hh, ow = (ww + SS) % Ww;
    size_t dst = ((size_t)(b * Hh + oh) * Ww + ow) * C;

    const float* src = g_q + (size_t)t * C;
    float v[6];
    float s = 0.0f;
    #pragma unroll
    for (int i = 0; i < 6; ++i) { v[i] = src[lane + i * 32]; s += v[i]; }
    float mean = warp_sum(s) * (1.0f / C);
    float vr = 0.0f;
    #pragma unroll
    for (int i = 0; i < 6; ++i) { float d = v[i] - mean; vr += d * d; }
    float rsig = rsqrtf(warp_sum(vr) * (1.0f / C) + EPS);
    #pragma unroll
    for (int i = 0; i < 6; ++i) {
        int c = lane + i * 32;
        float ln = (v[i] - mean) * rsig * g1[c] + b1[c];
        float hv = x[dst + c] + ln;
        g_k [dst + c] = hv;
        g_kh[dst + c] = __float2half(hv);
    }
}

// out[t] = hidden[t] + LN2(mlp[t]). 8 tokens/block.
__global__ __launch_bounds__(256)
void final_kernel(const float* __restrict__ g2, const float* __restrict__ b2,
                  float* __restrict__ out) {
    int warp = threadIdx.x >> 5, lane = threadIdx.x & 31;
    int t = blockIdx.x * 8 + warp;
    const float* src = g_v + (size_t)t * C;
    float v[6];
    float s = 0.0f;
    #pragma unroll
    for (int i = 0; i < 6; ++i) { v[i] = src[lane + i * 32]; s += v[i]; }
    float mean = warp_sum(s) * (1.0f / C);
    float vr = 0.0f;
    #pragma unroll
    for (int i = 0; i < 6; ++i) { float d = v[i] - mean; vr += d * d; }
    float rsig = rsqrtf(warp_sum(vr) * (1.0f / C) + EPS);
    #pragma unroll
    for (int i = 0; i < 6; ++i) {
        int c = lane + i * 32;
        float ln = (v[i] - mean) * rsig * g2[c] + b2[c];
        out[(size_t)t * C + c] = g_k[(size_t)t * C + c] + ln;
    }
}

} // namespace

// ============================================================================
extern "C" void kernel_launch(void* const* d_in, const int* in_sizes, int n_in,
                              void* d_out, int out_size) {
    const float* x      = (const float*)d_in[0];
    const float* ln1_g  = (const float*)d_in[1];
    const float* ln1_b  = (const float*)d_in[2];
    const float* ln2_g  = (const float*)d_in[3];
    const float* ln2_b  = (const float*)d_in[4];
    const float* q_w    = (const float*)d_in[5];
    const float* q_b    = (const float*)d_in[6];
    const float* k_w    = (const float*)d_in[7];
    const float* v_w    = (const float*)d_in[8];
    const float* v_b    = (const float*)d_in[9];
    const float* p_w    = (const float*)d_in[10];
    const float* p_b    = (const float*)d_in[11];
    const float* lscale = (const float*)d_in[12];
    const float* cpb_w0 = (const float*)d_in[13];
    const float* cpb_b0 = (const float*)d_in[14];
    const float* cpb_w1 = (const float*)d_in[15];
    const float* fc1_w  = (const float*)d_in[16];
    const float* fc1_b  = (const float*)d_in[17];
    const float* fc2_w  = (const float*)d_in[18];
    const float* fc2_b  = (const float*)d_in[19];
    float* out = (float*)d_out;

    float *p_qkv, *p_q, *p_v, *p_bqkv;
    __half *p_xh, *p_winh, *p_kh, *p_m1h, *p_wqkvT, *p_pwT, *p_fc1T, *p_fc2T;
    cudaGetSymbolAddress((void**)&p_xh,    g_xh);
    cudaGetSymbolAddress((void**)&p_qkv,   g_qkv);
    cudaGetSymbolAddress((void**)&p_winh,  g_winh);
    cudaGetSymbolAddress((void**)&p_q,     g_q);
    cudaGetSymbolAddress((void**)&p_kh,    g_kh);
    cudaGetSymbolAddress((void**)&p_v,     g_v);
    cudaGetSymbolAddress((void**)&p_m1h,   g_mlp1h);
    cudaGetSymbolAddress((void**)&p_bqkv,  g_bqkv);
    cudaGetSymbolAddress((void**)&p_wqkvT, g_wqkvT);
    cudaGetSymbolAddress((void**)&p_pwT,   g_pwT);
    cudaGetSymbolAddress((void**)&p_fc1T,  g_fc1T);
    cudaGetSymbolAddress((void**)&p_fc2T,  g_fc2T);

    // 1) all prep in ONE launch (x->half, CPB table, weight packs)
    prep_kernel<<<NB_PREP, 256>>>(x, cpb_w0, cpb_b0, cpb_w1, lscale,
                                  q_w, k_w, v_w, q_b, v_b, p_w, fc1_w, fc2_w);

    // 2) fused shift+window-gather + QKV GEMM  (A = xh, permuted rows)
    dim3 gQKV(QKVC / GBN, T / GBM);
    h16gemm_kernel<<<gQKV, 128>>>(p_xh, p_wqkvT, p_bqkv, p_qkv, nullptr,
                                  T, QKVC, C, 0, 1);

    // 3) fused attention -> g_winh (half)
    attn_kernel<<<BW * NH, 128>>>();

    // 4) output projection (A = attn out, half) -> g_q fp32
    dim3 gC(C / GBN, T / GBM);
    h16gemm_kernel<<<gC, 128>>>(p_winh, p_pwT, p_b, p_q, nullptr,
                                T, C, C, 0, 0);

    // 5) window reverse + un-shift + LN1 + residual -> hidden fp32 + half
    postattn_kernel<<<T / 8, 256>>>(x, ln1_g, ln1_b);

    // 6) fc1 + GELU (A = hidden half) -> g_mlp1h half
    dim3 gF1(C4 / GBN, T / GBM);
    h16gemm_kernel<<<gF1, 128>>>(p_kh, p_fc1T, fc1_b, nullptr, p_m1h,
                                 T, C4, C, 1, 0);

    // 7) fc2 (A = mlp1 half) -> g_v fp32
    h16gemm_kernel<<<gC, 128>>>(p_m1h, p_fc2T, fc2_b, p_v, nullptr,
                                T, C, C4, 0, 0);

    // 8) hidden + LN2(mlp) -> out
    final_kernel<<<T / 8, 256>>>(ln2_g, ln2_b, out);
}

// round 17
// speedup vs baseline: 1.0954x; 1.0532x over previous
#include <cuda_runtime.h>
#include <cuda_fp16.h>
#include <math.h>
#include <stdint.h>

namespace {

constexpr int Bb  = 8;
constexpr int Hh  = 112;
constexpr int Ww  = 112;
constexpr int C   = 192;
constexpr int NH  = 6;
constexpr int HD  = 32;      // C / NH
constexpr int WS  = 7;
constexpr int SS  = 3;
constexpr int N   = 49;      // WS*WS
constexpr int WG  = Hh / WS; // 16
constexpr int NW  = WG * WG; // 256
constexpr int BW  = Bb * NW; // 2048
constexpr int T   = BW * N;  // 100352 tokens
constexpr int C4  = 4 * C;   // 768
constexpr int QKVC = 3 * C;  // 576
constexpr float EPS    = 1e-5f;
constexpr float LOG100 = 4.605170185988091f;

// ---------------- scratch (static device globals; no allocation) -----------
__device__ __half g_xh   [(size_t)T * C];    // input x as half (natural layout)
__device__ float  g_qkv  [(size_t)T * QKVC]; // fused q|k|v (window-token layout)
__device__ __half g_winh [(size_t)T * C];    // attn output, half (window layout)
__device__ float  g_q    [(size_t)T * C];    // proj output
__device__ float  g_k    [(size_t)T * C];    // hidden fp32 (natural layout)
__device__ __half g_kh   [(size_t)T * C];    // hidden half (natural layout)
__device__ float  g_v    [(size_t)T * C];    // mlp output
__device__ __half g_mlp1h[(size_t)T * C4];   // fc1 output, half
__device__ __half g_wqkvT[QKVC * C];         // packed qkv weight, transposed, half
__device__ __half g_pwT  [C * C];            // proj weight transposed
__device__ __half g_fc1T [C4 * C];           // fc1 weight transposed
__device__ __half g_fc2T [C * C4];           // fc2 weight transposed
__device__ float g_bqkv[QKVC];               // packed qkv bias
__device__ float g_cpb [169 * NH];           // 16*sigmoid(CPB bias) table
__device__ float g_scl [NH];                 // per-head logit scale

__device__ __forceinline__ uint32_t pack_half2(float x, float y) {
    __half2 h = __floats2half2_rn(x, y);
    return *reinterpret_cast<uint32_t*>(&h);
}

// ================= merged prep kernel (one launch, block-range dispatch) ====
constexpr int NB_CVT = (int)((size_t)T * C / 4 / 256);  // 18816
constexpr int B_CPB0 = NB_CVT;
constexpr int B_QKV0 = B_CPB0 + 169;
constexpr int B_PW0  = B_QKV0 + QKVC;
constexpr int B_FC10 = B_PW0 + C;
constexpr int B_FC20 = B_FC10 + C4;
constexpr int NB_PREP = B_FC20 + C;

__global__ __launch_bounds__(256)
void prep_kernel(const float* __restrict__ x,
                 const float* __restrict__ cpb_w0, const float* __restrict__ cpb_b0,
                 const float* __restrict__ cpb_w1, const float* __restrict__ ls,
                 const float* __restrict__ qw, const float* __restrict__ kw,
                 const float* __restrict__ vw, const float* __restrict__ qb,
                 const float* __restrict__ vb,
                 const float* __restrict__ pw,
                 const float* __restrict__ fc1w, const float* __restrict__ fc2w) {
    int blk = blockIdx.x;
    int tid = threadIdx.x;

    if (blk < NB_CVT) {
        size_t i = ((size_t)blk * 256 + tid) * 4;
        float4 u = *reinterpret_cast<const float4*>(x + i);
        uint2 p = make_uint2(pack_half2(u.x, u.y), pack_half2(u.z, u.w));
        *reinterpret_cast<uint2*>(g_xh + i) = p;
        return;
    }
    if (blk < B_QKV0) {
        int r = blk - B_CPB0;          // 0..168
        __shared__ float part[256][NH];
        int ri = r / 13, rj = r % 13;
        float t0 = (ri - 6) * (8.0f / 6.0f);
        float t1 = (rj - 6) * (8.0f / 6.0f);
        float v0 = copysignf(log2f(fabsf(t0) + 1.0f) * (1.0f / 3.0f), t0);
        float v1 = copysignf(log2f(fabsf(t1) + 1.0f) * (1.0f / 3.0f), t1);
        float acc[NH];
        #pragma unroll
        for (int h = 0; h < NH; ++h) acc[h] = 0.0f;
        for (int j = tid; j < 512; j += 256) {
            float hv = fmaxf(v0 * cpb_w0[j] + v1 * cpb_w0[512 + j] + cpb_b0[j], 0.0f);
            #pragma unroll
            for (int h = 0; h < NH; ++h) acc[h] += hv * cpb_w1[j * NH + h];
        }
        #pragma unroll
        for (int h = 0; h < NH; ++h) part[tid][h] = acc[h];
        __syncthreads();
        if (tid < NH) {
            float s = 0.0f;
            for (int i = 0; i < 256; ++i) s += part[i][tid];
            g_cpb[r * NH + tid] = 16.0f / (1.0f + expf(-s));
            if (r == 0) g_scl[tid] = expf(fminf(ls[tid], LOG100));
        }
        return;
    }
    if (blk < B_PW0) {
        int j = blk - B_QKV0;          // 0..575
        const float* src; int jj;
        if (j < C)            { src = qw; jj = j; }
        else if (j < 2 * C)   { src = kw; jj = j - C; }
        else                  { src = vw; jj = j - 2 * C; }
        for (int k = tid; k < C; k += 256)
            g_wqkvT[(size_t)j * C + k] = __float2half(src[(size_t)k * C + jj]);
        if (tid == 0) {
            float b;
            if (j < C)          b = qb[j];
            else if (j < 2 * C) b = 0.0f;
            else                b = vb[j - 2 * C];
            g_bqkv[j] = b;
        }
        return;
    }
    if (blk < B_FC10) {
        int n = blk - B_PW0;
        for (int k = tid; k < C; k += 256)
            g_pwT[(size_t)n * C + k] = __float2half(pw[(size_t)k * C + n]);
        return;
    }
    if (blk < B_FC20) {
        int n = blk - B_FC10;
        for (int k = tid; k < C; k += 256)
            g_fc1T[(size_t)n * C + k] = __float2half(fc1w[(size_t)k * C4 + n]);
        return;
    }
    {
        int n = blk - B_FC20;
        for (int k = tid; k < C4; k += 256)
            g_fc2T[(size_t)n * C4 + k] = __float2half(fc2w[(size_t)k * C + n]);
    }
}

// ---------------- fp16 tensor-core GEMM: C = act(A@B + bias) ---------------
// A: half [M][K] (optional shift-window row gather). BT: half [Nn][K].
// cp.async 3-stage pipeline, GBK=32, one __syncthreads per K-tile,
// ldmatrix.x4 fragment loads.
constexpr int GBM = 128, GBN = 64, GBK = 32, STAGES = 3;
constexpr int AST = 40;   // half stride per A row (32 + 8 pad)
constexpr int BST = 40;   // half stride per B col
constexpr int ASTAGE = GBM * AST;  // halves per A stage
constexpr int BSTAGE = GBN * BST;  // halves per B stage

__device__ __forceinline__ float gelu_tanh(float v) {
    return 0.5f * v * (1.0f + tanhf(0.7978845608028654f * (v + 0.044715f * v * v * v)));
}

__device__ __forceinline__ void mma_f16(float* d, const uint32_t* a, const uint32_t* b) {
    asm volatile(
        "mma.sync.aligned.m16n8k16.row.col.f32.f16.f16.f32 "
        "{%0,%1,%2,%3},{%4,%5,%6,%7},{%8,%9},{%0,%1,%2,%3};"
        : "+f"(d[0]), "+f"(d[1]), "+f"(d[2]), "+f"(d[3])
        : "r"(a[0]), "r"(a[1]), "r"(a[2]), "r"(a[3]), "r"(b[0]), "r"(b[1]));
}

__device__ __forceinline__ void ldmatrix_x4(uint32_t* r, const __half* p) {
    uint32_t addr = (uint32_t)__cvta_generic_to_shared(p);
    asm volatile("ldmatrix.sync.aligned.m8n8.x4.shared.b16 {%0,%1,%2,%3}, [%4];"
        : "=r"(r[0]), "=r"(r[1]), "=r"(r[2]), "=r"(r[3]) : "r"(addr));
}

__device__ __forceinline__ void cp_async16(uint32_t saddr, const void* g) {
    asm volatile("cp.async.cg.shared.global [%0], [%1], 16;" :: "r"(saddr), "l"(g));
}

__global__ __launch_bounds__(128)
void h16gemm_kernel(const __half* __restrict__ A, const __half* __restrict__ BT,
                    const float* __restrict__ bias, float* __restrict__ Cout,
                    __half* __restrict__ CoutH,
                    int M, int Nn, int K, int act, int gatherA) {
    __shared__ __half As[STAGES][ASTAGE];
    __shared__ __half Bs[STAGES][BSTAGE];

    int tid  = threadIdx.x;            // 0..127
    int lane = tid & 31;
    int warp = tid >> 5;               // 0..3
    int gid  = lane >> 2;              // 0..7
    int tg   = lane & 3;               // 0..3
    int bm = blockIdx.y * GBM;
    int bn = blockIdx.x * GBN;
    int warp_m = (warp >> 1) * 64;     // 0 or 64
    int warp_n = (warp & 1) * 32;      // 0 or 32

    // A staging: 4 x 16B chunks per thread per tile (128 rows x 32 halves)
    const __half* aSrc[4];
    uint32_t aOff[4];                  // half-offset within stage
    #pragma unroll
    for (int i = 0; i < 4; ++i) {
        int idx = tid + i * 128;        // uint4 index within tile
        int row = idx >> 2;             // 4 uint4 per row
        int k8  = (idx & 3) * 8;
        aOff[i] = row * AST + k8;
        int r = bm + row;
        size_t abase;
        if (gatherA) {
            int bw = r / N, n = r % N;
            int b  = bw / NW, w_ = bw % NW;
            int wy = w_ / WG, wx = w_ % WG;
            int hh = wy * WS + n / WS, ww = wx * WS + n % WS;
            int oh = (hh + SS) % Hh, ow = (ww + SS) % Ww;
            abase = ((size_t)(b * Hh + oh) * Ww + ow) * (size_t)K;
        } else {
            abase = (size_t)r * K;
        }
        aSrc[i] = A + abase + k8;
    }
    // B staging: 2 x 16B chunks per thread per tile (64 cols x 32 halves)
    const __half* bSrc[2];
    uint32_t bOff[2];
    #pragma unroll
    for (int i = 0; i < 2; ++i) {
        int idx = tid + i * 128;
        int col = idx >> 2;
        int k8  = (idx & 3) * 8;
        bOff[i] = col * BST + k8;
        bSrc[i] = BT + (size_t)(bn + col) * K + k8;
    }

    // ldmatrix per-lane base offsets (element index into a stage)
    int lm = lane >> 3;            // matrix id 0..3
    int l7 = lane & 7;
    int aLd[4];
    #pragma unroll
    for (int mt = 0; mt < 4; ++mt)
        aLd[mt] = (warp_m + mt * 16 + l7 + (lm & 1) * 8) * AST + (lm >> 1) * 8;
    int bLd[2];
    #pragma unroll
    for (int p = 0; p < 2; ++p)
        bLd[p] = (warp_n + p * 16 + l7 + (lm >> 1) * 8) * BST + (lm & 1) * 8;

    uint32_t asBase = (uint32_t)__cvta_generic_to_shared(&As[0][0]);
    uint32_t bsBase = (uint32_t)__cvta_generic_to_shared(&Bs[0][0]);

    float acc[4][4][4];
    #pragma unroll
    for (int mt = 0; mt < 4; ++mt)
        #pragma unroll
        for (int nt = 0; nt < 4; ++nt)
            #pragma unroll
            for (int e = 0; e < 4; ++e) acc[mt][nt][e] = 0.0f;

    int nTiles = K / GBK;

    // prologue: issue stages 0 and 1
    {
        #pragma unroll
        for (int i = 0; i < 4; ++i)
            cp_async16(asBase + aOff[i] * 2, aSrc[i]);
        #pragma unroll
        for (int i = 0; i < 2; ++i)
            cp_async16(bsBase + bOff[i] * 2, bSrc[i]);
        asm volatile("cp.async.commit_group;");
        if (nTiles > 1) {
            #pragma unroll
            for (int i = 0; i < 4; ++i)
                cp_async16(asBase + (ASTAGE + aOff[i]) * 2, aSrc[i] + GBK);
            #pragma unroll
            for (int i = 0; i < 2; ++i)
                cp_async16(bsBase + (BSTAGE + bOff[i]) * 2, bSrc[i] + GBK);
        }
        asm volatile("cp.async.commit_group;");
    }

    int stage = 0;
    for (int it = 0; it < nTiles; ++it) {
        asm volatile("cp.async.wait_group 1;");
        __syncthreads();

        // issue tile it+2 into stage (it+2)%3
        int nxt = it + 2;
        if (nxt < nTiles) {
            int ns = nxt - (nxt / STAGES) * STAGES;
            int off = nxt * GBK;
            #pragma unroll
            for (int i = 0; i < 4; ++i)
                cp_async16(asBase + (ns * ASTAGE + aOff[i]) * 2, aSrc[i] + off);
            #pragma unroll
            for (int i = 0; i < 2; ++i)
                cp_async16(bsBase + (ns * BSTAGE + bOff[i]) * 2, bSrc[i] + off);
        }
        asm volatile("cp.async.commit_group;");

        // compute: two k16 chunks from current stage, ldmatrix fragments
        const __half* as = As[stage];
        const __half* bs = Bs[stage];
        #pragma unroll
        for (int kk = 0; kk < GBK; kk += 16) {
            uint32_t af[4][4];
            #pragma unroll
            for (int mt = 0; mt < 4; ++mt)
                ldmatrix_x4(af[mt], &as[aLd[mt] + kk]);
            uint32_t bf[4][2];
            #pragma unroll
            for (int p = 0; p < 2; ++p) {
                uint32_t tmp[4];
                ldmatrix_x4(tmp, &bs[bLd[p] + kk]);
                bf[2 * p    ][0] = tmp[0]; bf[2 * p    ][1] = tmp[1];
                bf[2 * p + 1][0] = tmp[2]; bf[2 * p + 1][1] = tmp[3];
            }
            #pragma unroll
            for (int mt = 0; mt < 4; ++mt)
                #pragma unroll
                for (int nt = 0; nt < 4; ++nt)
                    mma_f16(acc[mt][nt], af[mt], bf[nt]);
        }
        if (++stage == STAGES) stage = 0;
    }

    // epilogue: bias + optional GELU; float2 or half2 stores (col even)
    #pragma unroll
    for (int mt = 0; mt < 4; ++mt) {
        #pragma unroll
        for (int r2 = 0; r2 < 2; ++r2) {
            int row = bm + warp_m + mt * 16 + gid + r2 * 8;
            #pragma unroll
            for (int nt = 0; nt < 4; ++nt) {
                int col = bn + warp_n + nt * 8 + tg * 2;
                float v0 = acc[mt][nt][r2 * 2 + 0];
                float v1 = acc[mt][nt][r2 * 2 + 1];
                if (bias) { v0 += bias[col]; v1 += bias[col + 1]; }
                if (act == 1) { v0 = gelu_tanh(v0); v1 = gelu_tanh(v1); }
                if (CoutH)
                    *reinterpret_cast<uint32_t*>(&CoutH[(size_t)row * Nn + col]) =
                        pack_half2(v0, v1);
                else
                    *reinterpret_cast<float2*>(&Cout[(size_t)row * Nn + col]) =
                        make_float2(v0, v1);
            }
        }
    }
}

// ---------------- fused per-(window,head) attention (tensor cores) ---------
constexpr int QKS = 40;   // half stride of qh/kh rows (20 uint32)
constexpr int VTS = 72;   // half stride of vT rows (36 uint32)

__global__ __launch_bounds__(128)
void attn_kernel() {
    int blk = blockIdx.x;          // 0..BW*NH-1
    int bw  = blk / NH, h = blk % NH;
    int tid = threadIdx.x;
    int warp = tid >> 5, lane = tid & 31;
    int gid  = lane >> 2, tg = lane & 3;

    __shared__ __half qh[64 * QKS];
    __shared__ __half kh[64 * QKS];
    __shared__ __half vT[32 * VTS];
    __shared__ float cpb_s[169];
    __shared__ int   joff_s[64];
    __shared__ int   rgn_s[64];
    __shared__ float scale_s;

    uint32_t* qh32 = reinterpret_cast<uint32_t*>(qh);
    uint32_t* kh32 = reinterpret_cast<uint32_t*>(kh);
    uint32_t* vT32 = reinterpret_cast<uint32_t*>(vT);

    for (int i = tid; i < 64 * QKS / 2; i += 128) { qh32[i] = 0u; kh32[i] = 0u; }
    for (int i = tid; i < 32 * VTS / 2; i += 128) vT32[i] = 0u;

    if (tid == 0) scale_s = g_scl[h];
    for (int r = tid; r < 169; r += 128) cpb_s[r] = g_cpb[r * NH + h];
    if (tid < 64) {
        int j = tid;
        if (j < N) {
            int jy = j / WS, jx = j % WS;
            joff_s[j] = (6 - jy) * 13 + (6 - jx);
            int w_ = bw % NW, wy = w_ / WG, wx = w_ % WG;
            int gh = wy * WS + jy, gw = wx * WS + jx;
            int rh = gh < Hh - WS ? 0 : (gh < Hh - SS ? 1 : 2);
            int rw = gw < Ww - WS ? 0 : (gw < Ww - SS ? 1 : 2);
            rgn_s[j] = rh * 3 + rw;
        } else { joff_s[j] = 0; rgn_s[j] = -1; }
    }
    __syncthreads();

    if (tid < 2 * N) {
        int isK = tid >= N;
        int r = isK ? tid - N : tid;
        const float* row = g_qkv + (size_t)(bw * N + r) * QKVC + h * HD + (isK ? C : 0);
        float4 u[8];
        float ssum = 0.0f;
        #pragma unroll
        for (int d4 = 0; d4 < 8; ++d4) {
            u[d4] = *reinterpret_cast<const float4*>(row + d4 * 4);
            ssum += u[d4].x * u[d4].x + u[d4].y * u[d4].y
                  + u[d4].z * u[d4].z + u[d4].w * u[d4].w;
        }
        float inv = 1.0f / fmaxf(sqrtf(ssum), 1e-12f);
        if (!isK) inv *= scale_s;
        uint32_t* dst = (isK ? kh32 : qh32) + r * (QKS / 2);
        #pragma unroll
        for (int d4 = 0; d4 < 8; ++d4) {
            dst[d4 * 2 + 0] = pack_half2(u[d4].x * inv, u[d4].y * inv);
            dst[d4 * 2 + 1] = pack_half2(u[d4].z * inv, u[d4].w * inv);
        }
    }
    for (int e = tid; e < N * HD; e += 128) {
        int tok = e >> 5, d = e & 31;
        float v = g_qkv[(size_t)(bw * N + tok) * QKVC + 2 * C + h * HD + d];
        vT[d * VTS + tok] = __float2half(v);
    }
    __syncthreads();

    int m0 = warp * 16;
    int r0 = m0 + gid, r1 = r0 + 8;

    // ---- S = Q @ K^T  (16 x 64 per warp) ----
    float sacc[8][4];
    #pragma unroll
    for (int nt = 0; nt < 8; ++nt)
        #pragma unroll
        for (int e = 0; e < 4; ++e) sacc[nt][e] = 0.0f;

    #pragma unroll
    for (int ks = 0; ks < 2; ++ks) {
        uint32_t a[4];
        a[0] = qh32[ r0       * (QKS / 2) + ks * 8 + tg    ];
        a[1] = qh32[ r1       * (QKS / 2) + ks * 8 + tg    ];
        a[2] = qh32[ r0       * (QKS / 2) + ks * 8 + tg + 4];
        a[3] = qh32[ r1       * (QKS / 2) + ks * 8 + tg + 4];
        #pragma unroll
        for (int nt = 0; nt < 8; ++nt) {
            uint32_t b[2];
            int jr = nt * 8 + gid;
            b[0] = kh32[jr * (QKS / 2) + ks * 8 + tg    ];
            b[1] = kh32[jr * (QKS / 2) + ks * 8 + tg + 4];
            mma_f16(sacc[nt], a, b);
        }
    }

    // ---- bias + mask + softmax ----
    int ib0 = (r0 < N) ? (r0 / WS) * 13 + (r0 % WS) : 0;
    int ib1 = (r1 < N) ? (r1 / WS) * 13 + (r1 % WS) : 0;
    int rg0 = (r0 < N) ? rgn_s[r0] : -2;
    int rg1 = (r1 < N) ? rgn_s[r1] : -2;

    float mx0 = -1e30f, mx1 = -1e30f;
    #pragma unroll
    for (int nt = 0; nt < 8; ++nt) {
        int j0 = nt * 8 + tg * 2, j1 = j0 + 1;
        int jo0 = joff_s[j0], jo1 = joff_s[j1];
        int rj0 = rgn_s[j0],  rj1 = rgn_s[j1];
        float v00 = (j0 < N) ? sacc[nt][0] + cpb_s[ib0 + jo0] + (rj0 == rg0 ? 0.f : -100.f) : -1e30f;
        float v01 = (j1 < N) ? sacc[nt][1] + cpb_s[ib0 + jo1] + (rj1 == rg0 ? 0.f : -100.f) : -1e30f;
        float v10 = (j0 < N) ? sacc[nt][2] + cpb_s[ib1 + jo0] + (rj0 == rg1 ? 0.f : -100.f) : -1e30f;
        float v11 = (j1 < N) ? sacc[nt][3] + cpb_s[ib1 + jo1] + (rj1 == rg1 ? 0.f : -100.f) : -1e30f;
        sacc[nt][0] = v00; sacc[nt][1] = v01; sacc[nt][2] = v10; sacc[nt][3] = v11;
        mx0 = fmaxf(mx0, fmaxf(v00, v01));
        mx1 = fmaxf(mx1, fmaxf(v10, v11));
    }
    mx0 = fmaxf(mx0, __shfl_xor_sync(0xffffffffu, mx0, 1));
    mx0 = fmaxf(mx0, __shfl_xor_sync(0xffffffffu, mx0, 2));
    mx1 = fmaxf(mx1, __shfl_xor_sync(0xffffffffu, mx1, 1));
    mx1 = fmaxf(mx1, __shfl_xor_sync(0xffffffffu, mx1, 2));

    float sm0 = 0.0f, sm1 = 0.0f;
    #pragma unroll
    for (int nt = 0; nt < 8; ++nt) {
        sacc[nt][0] = __expf(sacc[nt][0] - mx0);
        sacc[nt][1] = __expf(sacc[nt][1] - mx0);
        sacc[nt][2] = __expf(sacc[nt][2] - mx1);
        sacc[nt][3] = __expf(sacc[nt][3] - mx1);
        sm0 += sacc[nt][0] + sacc[nt][1];
        sm1 += sacc[nt][2] + sacc[nt][3];
    }
    sm0 += __shfl_xor_sync(0xffffffffu, sm0, 1);
    sm0 += __shfl_xor_sync(0xffffffffu, sm0, 2);
    sm1 += __shfl_xor_sync(0xffffffffu, sm1, 1);
    sm1 += __shfl_xor_sync(0xffffffffu, sm1, 2);
    float inv0 = 1.0f / sm0, inv1 = 1.0f / sm1;

    uint32_t ph0[8], ph1[8];
    #pragma unroll
    for (int nt = 0; nt < 8; ++nt) {
        ph0[nt] = pack_half2(sacc[nt][0] * inv0, sacc[nt][1] * inv0);
        ph1[nt] = pack_half2(sacc[nt][2] * inv1, sacc[nt][3] * inv1);
    }

    // ---- O = P @ V  (16 x 32 per warp) ----
    float oacc[4][4];
    #pragma unroll
    for (int nt = 0; nt < 4; ++nt)
        #pragma unroll
        for (int e = 0; e < 4; ++e) oacc[nt][e] = 0.0f;

    #pragma unroll
    for (int ks = 0; ks < 4; ++ks) {
        uint32_t a[4];
        a[0] = ph0[2 * ks];
        a[1] = ph1[2 * ks];
        a[2] = ph0[2 * ks + 1];
        a[3] = ph1[2 * ks + 1];
        #pragma unroll
        for (int nt = 0; nt < 4; ++nt) {
            uint32_t b[2];
            int dr = nt * 8 + gid;
            b[0] = vT32[dr * (VTS / 2) + ks * 8 + tg    ];
            b[1] = vT32[dr * (VTS / 2) + ks * 8 + tg + 4];
            mma_f16(oacc[nt], a, b);
        }
    }

    // store as half (proj GEMM consumes half A)
    __half* dst = g_winh + (size_t)bw * N * C + h * HD;
    #pragma unroll
    for (int nt = 0; nt < 4; ++nt) {
        int d0 = nt * 8 + tg * 2;
        if (r0 < N)
            *reinterpret_cast<uint32_t*>(&dst[(size_t)r0 * C + d0]) =
                pack_half2(oacc[nt][0], oacc[nt][1]);
        if (r1 < N)
            *reinterpret_cast<uint32_t*>(&dst[(size_t)r1 * C + d0]) =
                pack_half2(oacc[nt][2], oacc[nt][3]);
    }
}

// ---------------- warp-per-token LN kernels ---------------------------------
__device__ __forceinline__ float warp_sum(float v) {
    #pragma unroll
    for (int o = 16; o > 0; o >>= 1) v += __shfl_xor_sync(0xffffffffu, v, o);
    return v;
}

// hidden[dst] = x[dst] + LN1(proj[t]); fp32 + half copies. 8 tokens/block.
__global__ __launch_bounds__(256)
void postattn_kernel(const float* __restrict__ x,
                     const float* __restrict__ g1, const float* __restrict__ b1) {
    int warp = threadIdx.x >> 5, lane = threadIdx.x & 31;
    int t = blockIdx.x * 8 + warp;
    int bw = t / N, n = t % N;
    int b  = bw / NW, w_ = bw % NW;
    int wy = w_ / WG, wx = w_ % WG;
    int hh = wy * WS + n / WS, ww = wx * WS + n % WS;
    int oh = (hh + SS) % Hh, ow = (ww + SS) % Ww;
    size_t dst = ((size_t)(b * Hh + oh) * Ww + ow) * C;

    const float* src = g_q + (size_t)t * C;
    float v[6];
    float s = 0.0f;
    #pragma unroll
    for (int i = 0; i < 6; ++i) { v[i] = src[lane + i * 32]; s += v[i]; }
    float mean = warp_sum(s) * (1.0f / C);
    float vr = 0.0f;
    #pragma unroll
    for (int i = 0; i < 6; ++i) { float d = v[i] - mean; vr += d * d; }
    float rsig = rsqrtf(warp_sum(vr) * (1.0f / C) + EPS);
    #pragma unroll
    for (int i = 0; i < 6; ++i) {
        int c = lane + i * 32;
        float ln = (v[i] - mean) * rsig * g1[c] + b1[c];
        float hv = x[dst + c] + ln;
        g_k [dst + c] = hv;
        g_kh[dst + c] = __float2half(hv);
    }
}

// out[t] = hidden[t] + LN2(mlp[t]). 8 tokens/block.
__global__ __launch_bounds__(256)
void final_kernel(const float* __restrict__ g2, const float* __restrict__ b2,
                  float* __restrict__ out) {
    int warp = threadIdx.x >> 5, lane = threadIdx.x & 31;
    int t = blockIdx.x * 8 + warp;
    const float* src = g_v + (size_t)t * C;
    float v[6];
    float s = 0.0f;
    #pragma unroll
    for (int i = 0; i < 6; ++i) { v[i] = src[lane + i * 32]; s += v[i]; }
    float mean = warp_sum(s) * (1.0f / C);
    float vr = 0.0f;
    #pragma unroll
    for (int i = 0; i < 6; ++i) { float d = v[i] - mean; vr += d * d; }
    float rsig = rsqrtf(warp_sum(vr) * (1.0f / C) + EPS);
    #pragma unroll
    for (int i = 0; i < 6; ++i) {
        int c = lane + i * 32;
        float ln = (v[i] - mean) * rsig * g2[c] + b2[c];
        out[(size_t)t * C + c] = g_k[(size_t)t * C + c] + ln;
    }
}

} // namespace

// ============================================================================
extern "C" void kernel_launch(void* const* d_in, const int* in_sizes, int n_in,
                              void* d_out, int out_size) {
    const float* x      = (const float*)d_in[0];
    const float* ln1_g  = (const float*)d_in[1];
    const float* ln1_b  = (const float*)d_in[2];
    const float* ln2_g  = (const float*)d_in[3];
    const float* ln2_b  = (const float*)d_in[4];
    const float* q_w    = (const float*)d_in[5];
    const float* q_b    = (const float*)d_in[6];
    const float* k_w    = (const float*)d_in[7];
    const float* v_w    = (const float*)d_in[8];
    const float* v_b    = (const float*)d_in[9];
    const float* p_w    = (const float*)d_in[10];
    const float* p_b    = (const float*)d_in[11];
    const float* lscale = (const float*)d_in[12];
    const float* cpb_w0 = (const float*)d_in[13];
    const float* cpb_b0 = (const float*)d_in[14];
    const float* cpb_w1 = (const float*)d_in[15];
    const float* fc1_w  = (const float*)d_in[16];
    const float* fc1_b  = (const float*)d_in[17];
    const float* fc2_w  = (const float*)d_in[18];
    const float* fc2_b  = (const float*)d_in[19];
    float* out = (float*)d_out;

    float *p_qkv, *p_q, *p_v, *p_bqkv;
    __half *p_xh, *p_winh, *p_kh, *p_m1h, *p_wqkvT, *p_pwT, *p_fc1T, *p_fc2T;
    cudaGetSymbolAddress((void**)&p_xh,    g_xh);
    cudaGetSymbolAddress((void**)&p_qkv,   g_qkv);
    cudaGetSymbolAddress((void**)&p_winh,  g_winh);
    cudaGetSymbolAddress((void**)&p_q,     g_q);
    cudaGetSymbolAddress((void**)&p_kh,    g_kh);
    cudaGetSymbolAddress((void**)&p_v,     g_v);
    cudaGetSymbolAddress((void**)&p_m1h,   g_mlp1h);
    cudaGetSymbolAddress((void**)&p_bqkv,  g_bqkv);
    cudaGetSymbolAddress((void**)&p_wqkvT, g_wqkvT);
    cudaGetSymbolAddress((void**)&p_pwT,   g_pwT);
    cudaGetSymbolAddress((void**)&p_fc1T,  g_fc1T);
    cudaGetSymbolAddress((void**)&p_fc2T,  g_fc2T);

    // 1) all prep in ONE launch (x->half, CPB table, weight packs)
    prep_kernel<<<NB_PREP, 256>>>(x, cpb_w0, cpb_b0, cpb_w1, lscale,
                                  q_w, k_w, v_w, q_b, v_b, p_w, fc1_w, fc2_w);

    // 2) fused shift+window-gather + QKV GEMM  (A = xh, permuted rows)
    dim3 gQKV(QKVC / GBN, T / GBM);
    h16gemm_kernel<<<gQKV, 128>>>(p_xh, p_wqkvT, p_bqkv, p_qkv, nullptr,
                                  T, QKVC, C, 0, 1);

    // 3) fused attention -> g_winh (half)
    attn_kernel<<<BW * NH, 128>>>();

    // 4) output projection (A = attn out, half) -> g_q fp32
    dim3 gC(C / GBN, T / GBM);
    h16gemm_kernel<<<gC, 128>>>(p_winh, p_pwT, p_b, p_q, nullptr,
                                T, C, C, 0, 0);

    // 5) window reverse + un-shift + LN1 + residual -> hidden fp32 + half
    postattn_kernel<<<T / 8, 256>>>(x, ln1_g, ln1_b);

    // 6) fc1 + GELU (A = hidden half) -> g_mlp1h half
    dim3 gF1(C4 / GBN, T / GBM);
    h16gemm_kernel<<<gF1, 128>>>(p_kh, p_fc1T, fc1_b, nullptr, p_m1h,
                                 T, C4, C, 1, 0);

    // 7) fc2 (A = mlp1 half) -> g_v fp32
    h16gemm_kernel<<<gC, 128>>>(p_m1h, p_fc2T, fc2_b, p_v, nullptr,
                                T, C, C4, 0, 0);

    // 8) hidden + LN2(mlp) -> out
    final_kernel<<<T / 8, 256>>>(ln2_g, ln2_b, out);
}